// round 12
// baseline (speedup 1.0000x reference)
#include <cuda_runtime.h>
#include <cuda_fp16.h>
#include <cstdint>

// Problem constants (shapes fixed by the dataset)
#define MAX_NODES 50000
#define F_IN   32
#define F_OUT  32
#define NB     4
#define K16    (NB * NB)          // 16 basis products
#define YROW   (K16 * F_OUT)      // 512 values per node (j = kx*128 + ky*32 + ch)

// Scratch: Y[n, j] = sum_i x_j[n,i] * W[j>>5, i, j&31]  in fp16 (51.2 MB)
__device__ __half g_Y[(size_t)MAX_NODES * YROW];

struct alignas(8) Half4 { __half2 a, b; };

// ---------------------------------------------------------------------------
// Kernel 1: zero out, then Y = X @ Wbig via HMMA m16n8k16 (fp16 in, fp32 acc).
//   Wbig[i, j] = w[j>>5][i][j&31]  ->  one GEMM [N,32] x [32,512].
// 256 threads = 8 warps; each warp owns a 16-node m-tile, sweeps 64 n-tiles
// in 2 phases of 32. D fragments are staged in a per-warp smem tile and
// flushed with coalesced 512B row stores.            (round-8, measured best)
// ---------------------------------------------------------------------------
#define WPAD  40    // halves per Ws row (80 B stride: ldmatrix conflict-free)
#define DCOLS 264   // 256 data halves + 8 pad (row stride 528 B, conflict-free)

__global__ __launch_bounds__(256, 2) void build_Y_mma(
    const float* __restrict__ x,     // [N, 32] fp32
    const float* __restrict__ w,     // [16, 32, 32] fp32
    float4*      __restrict__ out4,  // [N*32/4] -- zeroed here
    int n_nodes)
{
    extern __shared__ __half smem[];
    __half* Ws = smem;                                 // 512*WPAD = 40 KB
    __half* Dw = smem + 512 * WPAD +
                 (threadIdx.x >> 5) * (16 * DCOLS);    // per-warp 16x264 tile

    // Zero the output (poisoned by harness); K2 runs after this kernel.
    {
        int n4 = n_nodes * (F_OUT / 4);
        for (int i = blockIdx.x * blockDim.x + threadIdx.x; i < n4;
             i += gridDim.x * blockDim.x)
            out4[i] = make_float4(0.f, 0.f, 0.f, 0.f);
    }

    // Stage WbigT[j][i] = w[k][i][o],  j = k*32 + o  (coalesced global reads)
    for (int idx = threadIdx.x; idx < K16 * F_IN * F_OUT; idx += blockDim.x) {
        int k = idx >> 10, i = (idx >> 5) & 31, o = idx & 31;
        Ws[(k * 32 + o) * WPAD + i] = __float2half_rn(w[idx]);
    }
    __syncthreads();

    const int lane = threadIdx.x & 31;

    // ldmatrix.x2 source addresses for B (lanes 0-7: mat0, 8-15: mat1)
    const unsigned bbase = (unsigned)__cvta_generic_to_shared(Ws);
    const int brow  = lane & 7;          // row within n-tile
    const int bhalf = (lane >> 3) & 1;   // mat1 -> k columns +8

    const int mtiles = n_nodes >> 4;     // N divisible by 16 (50000)
    const int warp_gl = blockIdx.x * 8 + (threadIdx.x >> 5);

    for (int mt = warp_gl; mt < mtiles; mt += gridDim.x * 8) {
        const int n0 = mt << 4;

        // A fragments: 2 k-chunks x 4 pairs, straight from global fp32.
        // pair p: row = n0 + l/4 + 8*(p&1), col = kc*16 + (l%4)*2 + 8*(p>>1)
        uint32_t afr[2][4];
        const int ar = n0 + (lane >> 2);
        const int ac = (lane & 3) * 2;
        #pragma unroll
        for (int kc = 0; kc < 2; kc++)
            #pragma unroll
            for (int p = 0; p < 4; p++) {
                int r = ar + ((p & 1) << 3);
                int cc = kc * 16 + ac + ((p >> 1) << 3);
                float2 v = *(const float2*)&x[r * F_IN + cc];
                __half2 h = __floats2half2_rn(v.x, v.y);
                afr[kc][p] = *(uint32_t*)&h;
            }

        __half* d_lo = &Dw[(lane >> 2) * DCOLS + ac];       // row l/4
        __half* d_hi = &Dw[((lane >> 2) + 8) * DCOLS + ac]; // row l/4 + 8

        #pragma unroll
        for (int ph = 0; ph < 2; ph++) {
            #pragma unroll 4
            for (int ntl = 0; ntl < 32; ntl++) {
                const int nt = ph * 32 + ntl;
                unsigned s0 = bbase +
                    (((nt * 8 + brow) * WPAD) + bhalf * 8) * 2u;
                uint32_t b00, b01, b10, b11;
                asm volatile("ldmatrix.sync.aligned.m8n8.x2.shared.b16 {%0,%1}, [%2];"
                             : "=r"(b00), "=r"(b01) : "r"(s0));
                asm volatile("ldmatrix.sync.aligned.m8n8.x2.shared.b16 {%0,%1}, [%2];"
                             : "=r"(b10), "=r"(b11) : "r"(s0 + 32u));

                float d0 = 0.f, d1 = 0.f, d2 = 0.f, d3 = 0.f;
                asm volatile(
                    "mma.sync.aligned.m16n8k16.row.col.f32.f16.f16.f32 "
                    "{%0,%1,%2,%3}, {%4,%5,%6,%7}, {%8,%9}, {%0,%1,%2,%3};"
                    : "+f"(d0), "+f"(d1), "+f"(d2), "+f"(d3)
                    : "r"(afr[0][0]), "r"(afr[0][1]), "r"(afr[0][2]), "r"(afr[0][3]),
                      "r"(b00), "r"(b01));
                asm volatile(
                    "mma.sync.aligned.m16n8k16.row.col.f32.f16.f16.f32 "
                    "{%0,%1,%2,%3}, {%4,%5,%6,%7}, {%8,%9}, {%0,%1,%2,%3};"
                    : "+f"(d0), "+f"(d1), "+f"(d2), "+f"(d3)
                    : "r"(afr[1][0]), "r"(afr[1][1]), "r"(afr[1][2]), "r"(afr[1][3]),
                      "r"(b10), "r"(b11));

                // Stage D in smem (conflict-free STS.32)
                *(__half2*)&d_lo[ntl * 8] = __floats2half2_rn(d0, d1);
                *(__half2*)&d_hi[ntl * 8] = __floats2half2_rn(d2, d3);
            }
            __syncwarp();

            // Coalesced flush: 16 rows x 512 B; one row per STG.128 instr
            #pragma unroll
            for (int it = 0; it < 16; it++) {
                int i = it * 32 + lane;
                int r = i >> 5, c = i & 31;
                *(int4*)&g_Y[(size_t)(n0 + r) * YROW + ph * 256 + c * 8] =
                    *(const int4*)&Dw[r * DCOLS + c * 8];
            }
            __syncwarp();
        }
    }
}

// ---------------------------------------------------------------------------
// Kernel 2: bilinear gather from fp16 Y + vectorized fp32 reduction scatter.
// Measured-best per-edge access shape (8 threads/edge, 4x LDG.64 corners,
// one RED.v4 per thread) with FOUR edges per thread (e + j*Eq) for maximum
// memory-level parallelism: 16 independent corner loads in flight per thread
// before any math. All four index/attr streams stay fully coalesced.
// ---------------------------------------------------------------------------
#define NE 4   // edges per thread

__global__ __launch_bounds__(256) void edge_msg_kernel(
    const int*    __restrict__ ei,   // [2, E] : row0 = dst, row1 = src
    const float2* __restrict__ ea,   // [E]
    float*        __restrict__ out,  // [N, 32]
    int E, int Eq)
{
    const int t = blockIdx.x * blockDim.x + threadIdx.x;
    const int e0 = t >> 3;           // 8 threads per edge
    const int c = (t & 7) << 2;      // base of this thread's 4 outputs
    if (e0 >= Eq) return;

    int   dst[NE], src[NE];
    float cc[NE][4];
    int   koff[NE];
    bool  has[NE];

    // ---- metadata + coefficients for all edges ----
    #pragma unroll
    for (int j = 0; j < NE; j++) {
        int e = e0 + j * Eq;
        has[j] = (e < E);
        int es = has[j] ? e : e0;
        dst[j] = __ldg(&ei[es]);
        src[j] = __ldg(&ei[E + es]);
        float2 a = __ldg(&ea[es]);

        float ux = fminf(fmaxf((a.x + 1.0f) * 1.5f, 0.0f), 3.0f);
        float uy = fminf(fmaxf((a.y + 1.0f) * 1.5f, 0.0f), 3.0f);
        int jx = min((int)ux, 2), jy = min((int)uy, 2);
        float tx = ux - (float)jx, ty = uy - (float)jy;
        float sx = 1.0f - tx, sy = 1.0f - ty;
        cc[j][0] = sx * sy; cc[j][1] = sx * ty;
        cc[j][2] = tx * sy; cc[j][3] = tx * ty;
        koff[j] = (jx * NB + jy) * F_OUT;
    }

    // ---- issue all 16 corner loads back-to-back (max MLP) ----
    Half4 v[NE][4];
    #pragma unroll
    for (int j = 0; j < NE; j++) {
        const __half* Yp = &g_Y[(size_t)src[j] * YROW + koff[j] + c];
        v[j][0] = *(const Half4*)(Yp);
        v[j][1] = *(const Half4*)(Yp + 32);
        v[j][2] = *(const Half4*)(Yp + 128);
        v[j][3] = *(const Half4*)(Yp + 160);
    }

    // ---- math + scatter per edge ----
    #pragma unroll
    for (int j = 0; j < NE; j++) {
        if (!has[j]) continue;
        float2 f0a = __half22float2(v[j][0].a), f0b = __half22float2(v[j][0].b);
        float2 f1a = __half22float2(v[j][1].a), f1b = __half22float2(v[j][1].b);
        float2 f2a = __half22float2(v[j][2].a), f2b = __half22float2(v[j][2].b);
        float2 f3a = __half22float2(v[j][3].a), f3b = __half22float2(v[j][3].b);
        float r0 = cc[j][0]*f0a.x + cc[j][1]*f1a.x + cc[j][2]*f2a.x + cc[j][3]*f3a.x;
        float r1 = cc[j][0]*f0a.y + cc[j][1]*f1a.y + cc[j][2]*f2a.y + cc[j][3]*f3a.y;
        float r2 = cc[j][0]*f0b.x + cc[j][1]*f1b.x + cc[j][2]*f2b.x + cc[j][3]*f3b.x;
        float r3 = cc[j][0]*f0b.y + cc[j][1]*f1b.y + cc[j][2]*f2b.y + cc[j][3]*f3b.y;
        float* dp = out + dst[j] * F_OUT + c;   // 16B-aligned
        asm volatile("red.global.add.v4.f32 [%0], {%1, %2, %3, %4};"
                     :: "l"(dp), "f"(r0), "f"(r1), "f"(r2), "f"(r3)
                     : "memory");
    }
}

// ---------------------------------------------------------------------------
// Launch
// Inputs (metadata order): x_i, x_j, edge_index, edge_attr, weight
// ---------------------------------------------------------------------------
extern "C" void kernel_launch(void* const* d_in, const int* in_sizes, int n_in,
                              void* d_out, int out_size)
{
    const float*  x_j = (const float*) d_in[1];
    const int*    ei  = (const int*)   d_in[2];
    const float2* ea  = (const float2*)d_in[3];
    const float*  w   = (const float*) d_in[4];
    float* out = (float*)d_out;

    const int n_nodes = in_sizes[0] / F_IN;
    const int E       = in_sizes[2] / 2;

    // K1: zero out + build Y via tensor cores, smem-staged coalesced stores
    {
        static const int smem_bytes =
            (512 * WPAD + 8 * 16 * DCOLS) * (int)sizeof(__half);  // ~106 KB
        cudaFuncSetAttribute(build_Y_mma,
                             cudaFuncAttributeMaxDynamicSharedMemorySize, smem_bytes);
        int mtiles = n_nodes >> 4;                 // 3125
        int blocks = (mtiles + 7) / 8;
        if (blocks > 296) blocks = 296;            // 2 blocks/SM, grid-stride
        build_Y_mma<<<blocks, 256, smem_bytes>>>(x_j, w, (float4*)d_out, n_nodes);
    }

    // K2: edge gather + reduction scatter, 4 edges per thread for MLP
    {
        int Eq = (E + NE - 1) / NE;
        long long threads = (long long)Eq * 8;
        int blocks = (int)((threads + 255) / 256);
        edge_msg_kernel<<<blocks, 256>>>(ei, ea, out, E, Eq);
    }

    (void)n_in; (void)out_size;
}

// round 13
// speedup vs baseline: 1.0344x; 1.0344x over previous
#include <cuda_runtime.h>
#include <cuda_fp16.h>
#include <cstdint>

// Problem constants (shapes fixed by the dataset)
#define MAX_NODES 50000
#define F_IN   32
#define F_OUT  32
#define NB     4
#define K16    (NB * NB)          // 16 basis products
#define YROW   (K16 * F_OUT)      // 512 values per node (j = kx*128 + ky*32 + ch)

// Scratch: Y[n, j] = sum_i x_j[n,i] * W[j>>5, i, j&31]  in fp16 (51.2 MB)
__device__ __half g_Y[(size_t)MAX_NODES * YROW];

// Dynamic tile ticket for K1 load balancing (zeroed via cudaMemsetAsync
// before each K1 launch; graph-capturable, no allocation).
__device__ int g_ticket;

struct alignas(8) Half4 { __half2 a, b; };

// ---------------------------------------------------------------------------
// Kernel 1: zero out, then Y = X @ Wbig via HMMA m16n8k16 (fp16 in, fp32 acc).
//   Wbig[i, j] = w[j>>5][i][j&31]  ->  one GEMM [N,32] x [32,512].
// 256 threads = 8 warps; each warp grabs 16-node m-tiles from a global atomic
// ticket (near-perfect balance vs static 1.32 tiles/warp), sweeps 64 n-tiles
// in 2 phases of 32. D fragments staged in a per-warp smem tile and flushed
// with coalesced 512B row stores.
// ---------------------------------------------------------------------------
#define WPAD  40    // halves per Ws row (80 B stride: ldmatrix conflict-free)
#define DCOLS 264   // 256 data halves + 8 pad (row stride 528 B, conflict-free)

__global__ __launch_bounds__(256, 2) void build_Y_mma(
    const float* __restrict__ x,     // [N, 32] fp32
    const float* __restrict__ w,     // [16, 32, 32] fp32
    float4*      __restrict__ out4,  // [N*32/4] -- zeroed here
    int n_nodes)
{
    extern __shared__ __half smem[];
    __half* Ws = smem;                                 // 512*WPAD = 40 KB
    __half* Dw = smem + 512 * WPAD +
                 (threadIdx.x >> 5) * (16 * DCOLS);    // per-warp 16x264 tile

    // Zero the output (poisoned by harness); K2 runs after this kernel.
    {
        int n4 = n_nodes * (F_OUT / 4);
        for (int i = blockIdx.x * blockDim.x + threadIdx.x; i < n4;
             i += gridDim.x * blockDim.x)
            out4[i] = make_float4(0.f, 0.f, 0.f, 0.f);
    }

    // Stage WbigT[j][i] = w[k][i][o],  j = k*32 + o  (coalesced global reads)
    for (int idx = threadIdx.x; idx < K16 * F_IN * F_OUT; idx += blockDim.x) {
        int k = idx >> 10, i = (idx >> 5) & 31, o = idx & 31;
        Ws[(k * 32 + o) * WPAD + i] = __float2half_rn(w[idx]);
    }
    __syncthreads();

    const int lane = threadIdx.x & 31;

    // ldmatrix.x2 source addresses for B (lanes 0-7: mat0, 8-15: mat1)
    const unsigned bbase = (unsigned)__cvta_generic_to_shared(Ws);
    const int brow  = lane & 7;          // row within n-tile
    const int bhalf = (lane >> 3) & 1;   // mat1 -> k columns +8

    const int mtiles = n_nodes >> 4;     // N divisible by 16 (50000)

    while (true) {
        // Grab next tile from the global ticket (warp-uniform).
        int mt;
        if (lane == 0) mt = atomicAdd(&g_ticket, 1);
        mt = __shfl_sync(0xffffffffu, mt, 0);
        if (mt >= mtiles) break;

        const int n0 = mt << 4;

        // A fragments: 2 k-chunks x 4 pairs, straight from global fp32.
        // pair p: row = n0 + l/4 + 8*(p&1), col = kc*16 + (l%4)*2 + 8*(p>>1)
        uint32_t afr[2][4];
        const int ar = n0 + (lane >> 2);
        const int ac = (lane & 3) * 2;
        #pragma unroll
        for (int kc = 0; kc < 2; kc++)
            #pragma unroll
            for (int p = 0; p < 4; p++) {
                int r = ar + ((p & 1) << 3);
                int cc = kc * 16 + ac + ((p >> 1) << 3);
                float2 v = *(const float2*)&x[r * F_IN + cc];
                __half2 h = __floats2half2_rn(v.x, v.y);
                afr[kc][p] = *(uint32_t*)&h;
            }

        __half* d_lo = &Dw[(lane >> 2) * DCOLS + ac];       // row l/4
        __half* d_hi = &Dw[((lane >> 2) + 8) * DCOLS + ac]; // row l/4 + 8

        #pragma unroll
        for (int ph = 0; ph < 2; ph++) {
            #pragma unroll 4
            for (int ntl = 0; ntl < 32; ntl++) {
                const int nt = ph * 32 + ntl;
                unsigned s0 = bbase +
                    (((nt * 8 + brow) * WPAD) + bhalf * 8) * 2u;
                uint32_t b00, b01, b10, b11;
                asm volatile("ldmatrix.sync.aligned.m8n8.x2.shared.b16 {%0,%1}, [%2];"
                             : "=r"(b00), "=r"(b01) : "r"(s0));
                asm volatile("ldmatrix.sync.aligned.m8n8.x2.shared.b16 {%0,%1}, [%2];"
                             : "=r"(b10), "=r"(b11) : "r"(s0 + 32u));

                float d0 = 0.f, d1 = 0.f, d2 = 0.f, d3 = 0.f;
                asm volatile(
                    "mma.sync.aligned.m16n8k16.row.col.f32.f16.f16.f32 "
                    "{%0,%1,%2,%3}, {%4,%5,%6,%7}, {%8,%9}, {%0,%1,%2,%3};"
                    : "+f"(d0), "+f"(d1), "+f"(d2), "+f"(d3)
                    : "r"(afr[0][0]), "r"(afr[0][1]), "r"(afr[0][2]), "r"(afr[0][3]),
                      "r"(b00), "r"(b01));
                asm volatile(
                    "mma.sync.aligned.m16n8k16.row.col.f32.f16.f16.f32 "
                    "{%0,%1,%2,%3}, {%4,%5,%6,%7}, {%8,%9}, {%0,%1,%2,%3};"
                    : "+f"(d0), "+f"(d1), "+f"(d2), "+f"(d3)
                    : "r"(afr[1][0]), "r"(afr[1][1]), "r"(afr[1][2]), "r"(afr[1][3]),
                      "r"(b10), "r"(b11));

                // Stage D in smem (conflict-free STS.32)
                *(__half2*)&d_lo[ntl * 8] = __floats2half2_rn(d0, d1);
                *(__half2*)&d_hi[ntl * 8] = __floats2half2_rn(d2, d3);
            }
            __syncwarp();

            // Coalesced flush: 16 rows x 512 B; one row per STG.128 instr
            #pragma unroll
            for (int it = 0; it < 16; it++) {
                int i = it * 32 + lane;
                int r = i >> 5, c = i & 31;
                *(int4*)&g_Y[(size_t)(n0 + r) * YROW + ph * 256 + c * 8] =
                    *(const int4*)&Dw[r * DCOLS + c * 8];
            }
            __syncwarp();
        }
    }
}

// ---------------------------------------------------------------------------
// Kernel 2: bilinear gather from fp16 Y + vectorized fp32 reduction scatter.
// Measured-best operating point (round 11): 8 threads/edge, 4x LDG.64 corner
// loads, one RED.v4 per thread, TWO edges per thread (e and e + E/2) for MLP.
// ---------------------------------------------------------------------------
__global__ __launch_bounds__(256) void edge_msg_kernel(
    const int*    __restrict__ ei,   // [2, E] : row0 = dst, row1 = src
    const float2* __restrict__ ea,   // [E]
    float*        __restrict__ out,  // [N, 32]
    int E, int Ehalf)
{
    const int t = blockIdx.x * blockDim.x + threadIdx.x;
    const int e0 = t >> 3;           // 8 threads per edge
    const int c = (t & 7) << 2;      // base of this thread's 4 outputs
    if (e0 >= Ehalf) return;
    const int e1 = e0 + Ehalf;
    const bool has1 = (e1 < E);

    // ---- gather both edges' metadata (independent loads) ----
    const int dst0 = __ldg(&ei[e0]);
    const int src0 = __ldg(&ei[E + e0]);
    const float2 a0 = __ldg(&ea[e0]);
    const int dst1 = has1 ? __ldg(&ei[e1]) : 0;
    const int src1 = has1 ? __ldg(&ei[E + e1]) : 0;
    const float2 a1 = has1 ? __ldg(&ea[e1]) : make_float2(0.f, 0.f);

    // ---- coefficients edge 0 ----
    float ux0 = fminf(fmaxf((a0.x + 1.0f) * 1.5f, 0.0f), 3.0f);
    float uy0 = fminf(fmaxf((a0.y + 1.0f) * 1.5f, 0.0f), 3.0f);
    int jx0 = min((int)ux0, 2), jy0 = min((int)uy0, 2);
    float tx0 = ux0 - (float)jx0, ty0 = uy0 - (float)jy0;
    float sx0 = 1.0f - tx0, sy0 = 1.0f - ty0;
    const float c00_0 = sx0 * sy0, c01_0 = sx0 * ty0,
                c10_0 = tx0 * sy0, c11_0 = tx0 * ty0;

    // ---- coefficients edge 1 ----
    float ux1 = fminf(fmaxf((a1.x + 1.0f) * 1.5f, 0.0f), 3.0f);
    float uy1 = fminf(fmaxf((a1.y + 1.0f) * 1.5f, 0.0f), 3.0f);
    int jx1 = min((int)ux1, 2), jy1 = min((int)uy1, 2);
    float tx1 = ux1 - (float)jx1, ty1 = uy1 - (float)jy1;
    float sx1 = 1.0f - tx1, sy1 = 1.0f - ty1;
    const float c00_1 = sx1 * sy1, c01_1 = sx1 * ty1,
                c10_1 = tx1 * sy1, c11_1 = tx1 * ty1;

    // ---- issue all 8 corner loads back-to-back (max MLP) ----
    // k = kx*4 + ky ; corner (jx,jy): +32 elems per ky step, +128 per kx step
    const __half* Y0 = &g_Y[(size_t)src0 * YROW + (jx0 * NB + jy0) * F_OUT + c];
    const __half* Y1 = &g_Y[(size_t)(has1 ? src1 : src0) * YROW
                            + (jx1 * NB + jy1) * F_OUT + c];
    Half4 v00_0 = *(const Half4*)(Y0);
    Half4 v01_0 = *(const Half4*)(Y0 + 32);
    Half4 v10_0 = *(const Half4*)(Y0 + 128);
    Half4 v11_0 = *(const Half4*)(Y0 + 160);
    Half4 v00_1 = *(const Half4*)(Y1);
    Half4 v01_1 = *(const Half4*)(Y1 + 32);
    Half4 v10_1 = *(const Half4*)(Y1 + 128);
    Half4 v11_1 = *(const Half4*)(Y1 + 160);

    // ---- edge 0 math + scatter ----
    {
        float2 f00a = __half22float2(v00_0.a), f00b = __half22float2(v00_0.b);
        float2 f01a = __half22float2(v01_0.a), f01b = __half22float2(v01_0.b);
        float2 f10a = __half22float2(v10_0.a), f10b = __half22float2(v10_0.b);
        float2 f11a = __half22float2(v11_0.a), f11b = __half22float2(v11_0.b);
        float r0 = c00_0*f00a.x + c01_0*f01a.x + c10_0*f10a.x + c11_0*f11a.x;
        float r1 = c00_0*f00a.y + c01_0*f01a.y + c10_0*f10a.y + c11_0*f11a.y;
        float r2 = c00_0*f00b.x + c01_0*f01b.x + c10_0*f10b.x + c11_0*f11b.x;
        float r3 = c00_0*f00b.y + c01_0*f01b.y + c10_0*f10b.y + c11_0*f11b.y;
        float* dp = out + dst0 * F_OUT + c;   // 16B-aligned
        asm volatile("red.global.add.v4.f32 [%0], {%1, %2, %3, %4};"
                     :: "l"(dp), "f"(r0), "f"(r1), "f"(r2), "f"(r3)
                     : "memory");
    }

    // ---- edge 1 math + scatter ----
    if (has1) {
        float2 f00a = __half22float2(v00_1.a), f00b = __half22float2(v00_1.b);
        float2 f01a = __half22float2(v01_1.a), f01b = __half22float2(v01_1.b);
        float2 f10a = __half22float2(v10_1.a), f10b = __half22float2(v10_1.b);
        float2 f11a = __half22float2(v11_1.a), f11b = __half22float2(v11_1.b);
        float r0 = c00_1*f00a.x + c01_1*f01a.x + c10_1*f10a.x + c11_1*f11a.x;
        float r1 = c00_1*f00a.y + c01_1*f01a.y + c10_1*f10a.y + c11_1*f11a.y;
        float r2 = c00_1*f00b.x + c01_1*f01b.x + c10_1*f10b.x + c11_1*f11b.x;
        float r3 = c00_1*f00b.y + c01_1*f01b.y + c10_1*f10b.y + c11_1*f11b.y;
        float* dp = out + dst1 * F_OUT + c;   // 16B-aligned
        asm volatile("red.global.add.v4.f32 [%0], {%1, %2, %3, %4};"
                     :: "l"(dp), "f"(r0), "f"(r1), "f"(r2), "f"(r3)
                     : "memory");
    }
}

// ---------------------------------------------------------------------------
// Launch
// Inputs (metadata order): x_i, x_j, edge_index, edge_attr, weight
// ---------------------------------------------------------------------------
extern "C" void kernel_launch(void* const* d_in, const int* in_sizes, int n_in,
                              void* d_out, int out_size)
{
    const float*  x_j = (const float*) d_in[1];
    const int*    ei  = (const int*)   d_in[2];
    const float2* ea  = (const float2*)d_in[3];
    const float*  w   = (const float*) d_in[4];
    float* out = (float*)d_out;

    const int n_nodes = in_sizes[0] / F_IN;
    const int E       = in_sizes[2] / 2;

    // Zero the tile ticket (graph-capturable async memset; no allocation)
    {
        void* tick = nullptr;
        cudaGetSymbolAddress(&tick, g_ticket);
        cudaMemsetAsync(tick, 0, sizeof(int));
    }

    // K1: zero out + build Y via tensor cores, ticket-balanced tiles
    {
        static const int smem_bytes =
            (512 * WPAD + 8 * 16 * DCOLS) * (int)sizeof(__half);  // ~106 KB
        cudaFuncSetAttribute(build_Y_mma,
                             cudaFuncAttributeMaxDynamicSharedMemorySize, smem_bytes);
        build_Y_mma<<<296, 256, smem_bytes>>>(x_j, w, (float4*)d_out, n_nodes);
    }

    // K2: edge gather + reduction scatter, 2 edges per thread for MLP
    {
        int Ehalf = (E + 1) >> 1;
        long long threads = (long long)Ehalf * 8;
        int blocks = (int)((threads + 255) / 256);
        edge_msg_kernel<<<blocks, 256>>>(ei, ea, out, E, Ehalf);
    }

    (void)n_in; (void)out_size;
}

// round 16
// speedup vs baseline: 1.0695x; 1.0339x over previous
#include <cuda_runtime.h>
#include <cuda_fp16.h>
#include <cstdint>

// Problem constants (shapes fixed by the dataset)
#define MAX_NODES 50000
#define F_IN   32
#define F_OUT  32
#define NB     4
#define K16    (NB * NB)          // 16 basis products
#define YROW   (K16 * F_OUT)      // 512 values per node (j = kx*128 + ky*32 + ch)

// Scratch: Y[n, j] = sum_i x_j[n,i] * W[j>>5, i, j&31]  in fp16 (51.2 MB)
__device__ __half g_Y[(size_t)MAX_NODES * YROW];

struct alignas(8) Half4 { __half2 a, b; };

// ---------------------------------------------------------------------------
// Kernel 1: zero out, then Y = X @ Wbig via HMMA m16n8k16 (fp16 in, fp32 acc).
//   Wbig[i, j] = w[j>>5][i][j&31]  ->  one GEMM [N,32] x [32,512].
// Work unit = (m-tile, phase): half a 16-node tile (32 of the 64 n-tiles).
// 6250 units over 2368 warps -> longest warp does 1.5 tile-equivalents vs 2.0
// with whole-tile units (utilization 66% -> 88%). Inner loop, D staging and
// flush are identical to the round-8 kernel (measured correct & fastest).
// ---------------------------------------------------------------------------
#define WPAD  40    // halves per Ws row (80 B stride: ldmatrix conflict-free)
#define DCOLS 264   // 256 data halves + 8 pad (row stride 528 B, conflict-free)

__global__ __launch_bounds__(256, 2) void build_Y_mma(
    const float* __restrict__ x,     // [N, 32] fp32
    const float* __restrict__ w,     // [16, 32, 32] fp32
    float4*      __restrict__ out4,  // [N*32/4] -- zeroed here
    int n_nodes, int total_warps)
{
    extern __shared__ __half smem[];
    __half* Ws = smem;                                 // 512*WPAD = 40 KB
    __half* Dw = smem + 512 * WPAD +
                 (threadIdx.x >> 5) * (16 * DCOLS);    // per-warp 16x264 tile

    // Zero the output (poisoned by harness); K2 runs after this kernel.
    {
        int n4 = n_nodes * (F_OUT / 4);
        for (int i = blockIdx.x * blockDim.x + threadIdx.x; i < n4;
             i += gridDim.x * blockDim.x)
            out4[i] = make_float4(0.f, 0.f, 0.f, 0.f);
    }

    // Stage WbigT[j][i] = w[k][i][o],  j = k*32 + o  (coalesced global reads)
    for (int idx = threadIdx.x; idx < K16 * F_IN * F_OUT; idx += blockDim.x) {
        int k = idx >> 10, i = (idx >> 5) & 31, o = idx & 31;
        Ws[(k * 32 + o) * WPAD + i] = __float2half_rn(w[idx]);
    }
    __syncthreads();

    const int lane = threadIdx.x & 31;

    // ldmatrix.x2 source addresses for B (lanes 0-7: mat0, 8-15: mat1)
    const unsigned bbase = (unsigned)__cvta_generic_to_shared(Ws);
    const int brow  = lane & 7;          // row within n-tile
    const int bhalf = (lane >> 3) & 1;   // mat1 -> k columns +8

    const int mtiles = n_nodes >> 4;     // N divisible by 16 (50000)
    const int nunits = mtiles * 2;       // (m-tile, phase) pairs
    const int warp_gl = blockIdx.x * 8 + (threadIdx.x >> 5);
    const int ac = (lane & 3) * 2;

    for (int u = warp_gl; u < nunits; u += total_warps) {
        const int mt = u >> 1;
        const int ph = u & 1;
        const int n0 = mt << 4;

        // A fragments: 2 k-chunks x 4 pairs, straight from global fp32.
        // pair p: row = n0 + l/4 + 8*(p&1), col = kc*16 + (l%4)*2 + 8*(p>>1)
        uint32_t afr[2][4];
        const int ar = n0 + (lane >> 2);
        #pragma unroll
        for (int kc = 0; kc < 2; kc++)
            #pragma unroll
            for (int p = 0; p < 4; p++) {
                int r = ar + ((p & 1) << 3);
                int cc = kc * 16 + ac + ((p >> 1) << 3);
                float2 v = *(const float2*)&x[r * F_IN + cc];
                __half2 h = __floats2half2_rn(v.x, v.y);
                afr[kc][p] = *(uint32_t*)&h;
            }

        __half* d_lo = &Dw[(lane >> 2) * DCOLS + ac];       // row l/4
        __half* d_hi = &Dw[((lane >> 2) + 8) * DCOLS + ac]; // row l/4 + 8

        #pragma unroll 4
        for (int ntl = 0; ntl < 32; ntl++) {
            const int nt = ph * 32 + ntl;
            unsigned s0 = bbase +
                (((nt * 8 + brow) * WPAD) + bhalf * 8) * 2u;
            uint32_t b00, b01, b10, b11;
            asm volatile("ldmatrix.sync.aligned.m8n8.x2.shared.b16 {%0,%1}, [%2];"
                         : "=r"(b00), "=r"(b01) : "r"(s0));
            asm volatile("ldmatrix.sync.aligned.m8n8.x2.shared.b16 {%0,%1}, [%2];"
                         : "=r"(b10), "=r"(b11) : "r"(s0 + 32u));

            float d0 = 0.f, d1 = 0.f, d2 = 0.f, d3 = 0.f;
            asm volatile(
                "mma.sync.aligned.m16n8k16.row.col.f32.f16.f16.f32 "
                "{%0,%1,%2,%3}, {%4,%5,%6,%7}, {%8,%9}, {%0,%1,%2,%3};"
                : "+f"(d0), "+f"(d1), "+f"(d2), "+f"(d3)
                : "r"(afr[0][0]), "r"(afr[0][1]), "r"(afr[0][2]), "r"(afr[0][3]),
                  "r"(b00), "r"(b01));
            asm volatile(
                "mma.sync.aligned.m16n8k16.row.col.f32.f16.f16.f32 "
                "{%0,%1,%2,%3}, {%4,%5,%6,%7}, {%8,%9}, {%0,%1,%2,%3};"
                : "+f"(d0), "+f"(d1), "+f"(d2), "+f"(d3)
                : "r"(afr[1][0]), "r"(afr[1][1]), "r"(afr[1][2]), "r"(afr[1][3]),
                  "r"(b10), "r"(b11));

            // Stage D in smem (conflict-free STS.32); ntl*8 + ac <= 254 < 264
            *(__half2*)&d_lo[ntl * 8] = __floats2half2_rn(d0, d1);
            *(__half2*)&d_hi[ntl * 8] = __floats2half2_rn(d2, d3);
        }
        __syncwarp();

        // Coalesced flush (round-8): 16 rows x 256 halves of this phase;
        // i = 0..511, r = i>>5 (0..15), c = i&31, c*8+8 <= 256 <= DCOLS.
        #pragma unroll
        for (int it = 0; it < 16; it++) {
            int i = it * 32 + lane;
            int r = i >> 5, c = i & 31;
            *(int4*)&g_Y[(size_t)(n0 + r) * YROW + ph * 256 + c * 8] =
                *(const int4*)&Dw[r * DCOLS + c * 8];
        }
        __syncwarp();
    }
}

// ---------------------------------------------------------------------------
// Kernel 2: bilinear gather from fp16 Y + vectorized fp32 reduction scatter.
// Measured-best operating point (round 11): 8 threads/edge, 4x LDG.64 corner
// loads, one RED.v4 per thread, TWO edges per thread (e and e + E/2) for MLP.
// ---------------------------------------------------------------------------
__global__ __launch_bounds__(256) void edge_msg_kernel(
    const int*    __restrict__ ei,   // [2, E] : row0 = dst, row1 = src
    const float2* __restrict__ ea,   // [E]
    float*        __restrict__ out,  // [N, 32]
    int E, int Ehalf)
{
    const int t = blockIdx.x * blockDim.x + threadIdx.x;
    const int e0 = t >> 3;           // 8 threads per edge
    const int c = (t & 7) << 2;      // base of this thread's 4 outputs
    if (e0 >= Ehalf) return;
    const int e1 = e0 + Ehalf;
    const bool has1 = (e1 < E);

    // ---- gather both edges' metadata (independent loads) ----
    const int dst0 = __ldg(&ei[e0]);
    const int src0 = __ldg(&ei[E + e0]);
    const float2 a0 = __ldg(&ea[e0]);
    const int dst1 = has1 ? __ldg(&ei[e1]) : 0;
    const int src1 = has1 ? __ldg(&ei[E + e1]) : 0;
    const float2 a1 = has1 ? __ldg(&ea[e1]) : make_float2(0.f, 0.f);

    // ---- coefficients edge 0 ----
    float ux0 = fminf(fmaxf((a0.x + 1.0f) * 1.5f, 0.0f), 3.0f);
    float uy0 = fminf(fmaxf((a0.y + 1.0f) * 1.5f, 0.0f), 3.0f);
    int jx0 = min((int)ux0, 2), jy0 = min((int)uy0, 2);
    float tx0 = ux0 - (float)jx0, ty0 = uy0 - (float)jy0;
    float sx0 = 1.0f - tx0, sy0 = 1.0f - ty0;
    const float c00_0 = sx0 * sy0, c01_0 = sx0 * ty0,
                c10_0 = tx0 * sy0, c11_0 = tx0 * ty0;

    // ---- coefficients edge 1 ----
    float ux1 = fminf(fmaxf((a1.x + 1.0f) * 1.5f, 0.0f), 3.0f);
    float uy1 = fminf(fmaxf((a1.y + 1.0f) * 1.5f, 0.0f), 3.0f);
    int jx1 = min((int)ux1, 2), jy1 = min((int)uy1, 2);
    float tx1 = ux1 - (float)jx1, ty1 = uy1 - (float)jy1;
    float sx1 = 1.0f - tx1, sy1 = 1.0f - ty1;
    const float c00_1 = sx1 * sy1, c01_1 = sx1 * ty1,
                c10_1 = tx1 * sy1, c11_1 = tx1 * ty1;

    // ---- issue all 8 corner loads back-to-back (max MLP) ----
    // k = kx*4 + ky ; corner (jx,jy): +32 elems per ky step, +128 per kx step
    const __half* Y0 = &g_Y[(size_t)src0 * YROW + (jx0 * NB + jy0) * F_OUT + c];
    const __half* Y1 = &g_Y[(size_t)(has1 ? src1 : src0) * YROW
                            + (jx1 * NB + jy1) * F_OUT + c];
    Half4 v00_0 = *(const Half4*)(Y0);
    Half4 v01_0 = *(const Half4*)(Y0 + 32);
    Half4 v10_0 = *(const Half4*)(Y0 + 128);
    Half4 v11_0 = *(const Half4*)(Y0 + 160);
    Half4 v00_1 = *(const Half4*)(Y1);
    Half4 v01_1 = *(const Half4*)(Y1 + 32);
    Half4 v10_1 = *(const Half4*)(Y1 + 128);
    Half4 v11_1 = *(const Half4*)(Y1 + 160);

    // ---- edge 0 math + scatter ----
    {
        float2 f00a = __half22float2(v00_0.a), f00b = __half22float2(v00_0.b);
        float2 f01a = __half22float2(v01_0.a), f01b = __half22float2(v01_0.b);
        float2 f10a = __half22float2(v10_0.a), f10b = __half22float2(v10_0.b);
        float2 f11a = __half22float2(v11_0.a), f11b = __half22float2(v11_0.b);
        float r0 = c00_0*f00a.x + c01_0*f01a.x + c10_0*f10a.x + c11_0*f11a.x;
        float r1 = c00_0*f00a.y + c01_0*f01a.y + c10_0*f10a.y + c11_0*f11a.y;
        float r2 = c00_0*f00b.x + c01_0*f01b.x + c10_0*f10b.x + c11_0*f11b.x;
        float r3 = c00_0*f00b.y + c01_0*f01b.y + c10_0*f10b.y + c11_0*f11b.y;
        float* dp = out + dst0 * F_OUT + c;   // 16B-aligned
        asm volatile("red.global.add.v4.f32 [%0], {%1, %2, %3, %4};"
                     :: "l"(dp), "f"(r0), "f"(r1), "f"(r2), "f"(r3)
                     : "memory");
    }

    // ---- edge 1 math + scatter ----
    if (has1) {
        float2 f00a = __half22float2(v00_1.a), f00b = __half22float2(v00_1.b);
        float2 f01a = __half22float2(v01_1.a), f01b = __half22float2(v01_1.b);
        float2 f10a = __half22float2(v10_1.a), f10b = __half22float2(v10_1.b);
        float2 f11a = __half22float2(v11_1.a), f11b = __half22float2(v11_1.b);
        float r0 = c00_1*f00a.x + c01_1*f01a.x + c10_1*f10a.x + c11_1*f11a.x;
        float r1 = c00_1*f00a.y + c01_1*f01a.y + c10_1*f10a.y + c11_1*f11a.y;
        float r2 = c00_1*f00b.x + c01_1*f01b.x + c10_1*f10b.x + c11_1*f11b.x;
        float r3 = c00_1*f00b.y + c01_1*f01b.y + c10_1*f10b.y + c11_1*f11b.y;
        float* dp = out + dst1 * F_OUT + c;   // 16B-aligned
        asm volatile("red.global.add.v4.f32 [%0], {%1, %2, %3, %4};"
                     :: "l"(dp), "f"(r0), "f"(r1), "f"(r2), "f"(r3)
                     : "memory");
    }
}

// ---------------------------------------------------------------------------
// Launch
// Inputs (metadata order): x_i, x_j, edge_index, edge_attr, weight
// ---------------------------------------------------------------------------
extern "C" void kernel_launch(void* const* d_in, const int* in_sizes, int n_in,
                              void* d_out, int out_size)
{
    const float*  x_j = (const float*) d_in[1];
    const int*    ei  = (const int*)   d_in[2];
    const float2* ea  = (const float2*)d_in[3];
    const float*  w   = (const float*) d_in[4];
    float* out = (float*)d_out;

    const int n_nodes = in_sizes[0] / F_IN;
    const int E       = in_sizes[2] / 2;

    // K1: zero out + build Y via tensor cores; half-tile (mt, ph) work units,
    // 2 blocks/SM (same smem layout as round-8: ~106 KB/block).
    {
        static const int smem_bytes =
            (512 * WPAD + 8 * 16 * DCOLS) * (int)sizeof(__half);  // ~106 KB
        cudaFuncSetAttribute(build_Y_mma,
                             cudaFuncAttributeMaxDynamicSharedMemorySize, smem_bytes);
        const int blocks = 296;                       // 2 per SM
        const int total_warps = blocks * 8;           // 2368
        build_Y_mma<<<blocks, 256, smem_bytes>>>(x_j, w, (float4*)d_out,
                                                 n_nodes, total_warps);
    }

    // K2: edge gather + reduction scatter, 2 edges per thread for MLP
    {
        int Ehalf = (E + 1) >> 1;
        long long threads = (long long)Ehalf * 8;
        int blocks = (int)((threads + 255) / 256);
        edge_msg_kernel<<<blocks, 256>>>(ei, ea, out, E, Ehalf);
    }

    (void)n_in; (void)out_size;
}